// round 8
// baseline (speedup 1.0000x reference)
#include <cuda_runtime.h>
#include <cuda_fp16.h>
#include <math.h>

// Problem constants (fixed by the dataset)
#define NN    10000          // nodes
#define EE    320000         // edges (before self loops)
#define ET    (EE + NN)      // edges incl. self loops
#define HH    4              // heads
#define CC    128            // channels per head
#define HC    (HH * CC)      // 512
#define CAP   512            // agg chunk size (edges per shared-mem chunk)
#define EB    4              // edges per thread in count/fill

// ---------------- scratch (static device globals; no allocs allowed) ----------
__device__ __align__(16) __half2 g_h2[NN * HC / 2];  // fp16 feats [N, H*C] (10.2 MB)
__device__ float g_asrc[NN * HH];       // per-node src attention logits [N,4]
__device__ float g_adst[NN * HH];       // per-node dst attention logits [N,4]
__device__ int   g_count[NN];           // in-degree counts
__device__ int   g_off[NN + 1];         // CSR offsets
__device__ int   g_cursor[NN];          // fill cursors
__device__ int   g_src[ET];             // edge sources sorted by destination
__device__ int   g_is64;                // 1 if edge buffer is int64, 0 if int32

// ---------------- setup: zero counters + detect edge dtype --------------------
__global__ void setup_kernel(const int* __restrict__ e32) {
    int i = blockIdx.x * blockDim.x + threadIdx.x;
    if (i < NN) { g_count[i] = 0; g_cursor[i] = 0; }
    if (blockIdx.x == 0) {
        __shared__ int bad;
        if (threadIdx.x == 0) bad = 0;
        __syncthreads();
        int any = 0;
        for (int k = threadIdx.x; k < 1024; k += blockDim.x)
            any |= (e32[2 * k + 1] != 0);
        if (any) atomicOr(&bad, 1);
        __syncthreads();
        if (threadIdx.x == 0) g_is64 = bad ? 0 : 1;
    }
}

// ---------------- GEMM + fused attention dots ---------------------------------
__global__ void __launch_bounds__(256) gemm_kernel(
        const float* __restrict__ x, const float* __restrict__ W,
        const float* __restrict__ att_src, const float* __restrict__ att_dst) {
    __shared__ float xs[16][128];
    __shared__ float ws[16][128];
    const int tx = threadIdx.x & 15;
    const int ty = threadIdx.x >> 4;
    const int row0 = blockIdx.x * 128;
    const int head = blockIdx.y;
    const int col0 = head * CC;

    float acc[8][8];
#pragma unroll
    for (int i = 0; i < 8; i++)
#pragma unroll
        for (int j = 0; j < 8; j++) acc[i][j] = 0.f;

    for (int kk = 0; kk < CC; kk += 16) {
        {
            int m = threadIdx.x >> 1;
            int gr = row0 + m;
#pragma unroll
            for (int q = 0; q < 2; q++) {
                int k4 = (threadIdx.x & 1) * 2 + q;
                float4 v = make_float4(0.f, 0.f, 0.f, 0.f);
                if (gr < NN) v = *(const float4*)&x[gr * CC + kk + k4 * 4];
                xs[k4 * 4 + 0][m] = v.x;
                xs[k4 * 4 + 1][m] = v.y;
                xs[k4 * 4 + 2][m] = v.z;
                xs[k4 * 4 + 3][m] = v.w;
            }
        }
        {
#pragma unroll
            for (int q = 0; q < 2; q++) {
                int t = threadIdx.x + q * 256;
                int k = t >> 5;
                int c4 = t & 31;
                float4 v = *(const float4*)&W[(kk + k) * HC + col0 + c4 * 4];
                *(float4*)&ws[k][c4 * 4] = v;
            }
        }
        __syncthreads();
#pragma unroll
        for (int k = 0; k < 16; k++) {
            float a[8], b[8];
#pragma unroll
            for (int i = 0; i < 8; i++) a[i] = xs[k][ty * 8 + i];
#pragma unroll
            for (int j = 0; j < 8; j++) b[j] = ws[k][tx * 8 + j];
#pragma unroll
            for (int i = 0; i < 8; i++)
#pragma unroll
                for (int j = 0; j < 8; j++) acc[i][j] += a[i] * b[j];
        }
        __syncthreads();
    }

#pragma unroll
    for (int i = 0; i < 8; i++) {
        int gr = row0 + ty * 8 + i;
        if (gr < NN) {
            union alignas(16) { __half2 h2[4]; float4 f4; } u;
#pragma unroll
            for (int j = 0; j < 4; j++)
                u.h2[j] = __floats2half2_rn(acc[i][2 * j], acc[i][2 * j + 1]);
            *(float4*)&g_h2[(size_t)gr * (HC / 2) + (col0 + tx * 8) / 2] = u.f4;
        }
    }

    float as[8], ad[8];
#pragma unroll
    for (int j = 0; j < 8; j++) {
        as[j] = att_src[head * CC + tx * 8 + j];
        ad[j] = att_dst[head * CC + tx * 8 + j];
    }
#pragma unroll
    for (int i = 0; i < 8; i++) {
        float vs = 0.f, vd = 0.f;
#pragma unroll
        for (int j = 0; j < 8; j++) { vs += acc[i][j] * as[j]; vd += acc[i][j] * ad[j]; }
#pragma unroll
        for (int off = 8; off > 0; off >>= 1) {
            vs += __shfl_down_sync(0xFFFFFFFFu, vs, off, 16);
            vd += __shfl_down_sync(0xFFFFFFFFu, vd, off, 16);
        }
        int gr = row0 + ty * 8 + i;
        if (tx == 0 && gr < NN) {
            g_asrc[gr * HH + head] = vs;
            g_adst[gr * HH + head] = vd;
        }
    }
}

// ---------------- edge fetch helper -------------------------------------------
__device__ __forceinline__ int edge_at(const void* edge, long long idx, int is64) {
    if (is64) return (int)((const long long*)edge)[idx];
    return ((const int*)edge)[idx];
}

// ---------------- count in-degrees: EB edges per thread (MLP) -----------------
__global__ void count_kernel(const void* __restrict__ edge) {
    int e0 = (blockIdx.x * blockDim.x + threadIdx.x) * EB;
    if (e0 >= ET) return;
    int is64 = g_is64;
    int d[EB];
#pragma unroll
    for (int q = 0; q < EB; q++) {
        int e = e0 + q;
        d[q] = -1;
        if (e < ET)
            d[q] = (e < EE) ? edge_at(edge, (long long)EE + e, is64) : (e - EE);
    }
#pragma unroll
    for (int q = 0; q < EB; q++)
        if ((unsigned)d[q] < NN) atomicAdd(&g_count[d[q]], 1);
}

// ---------------- exclusive scan of counts -> offsets (single block) ----------
__global__ void __launch_bounds__(1024) scan_kernel() {
    const int CH = 10;
    __shared__ int sc[NN];
    int tid = threadIdx.x;

    for (int i = tid; i < NN; i += 1024) sc[i] = g_count[i];
    __syncthreads();

    int base = tid * CH;
    int vals[CH];
    int tsum = 0;
#pragma unroll
    for (int c = 0; c < CH; c++) {
        int idx = base + c;
        int v = (idx < NN) ? sc[idx] : 0;
        vals[c] = v;
        tsum += v;
    }
    int lane = tid & 31, wid = tid >> 5;
    int inc = tsum;
#pragma unroll
    for (int off = 1; off < 32; off <<= 1) {
        int y = __shfl_up_sync(0xFFFFFFFFu, inc, off);
        if (lane >= off) inc += y;
    }
    __shared__ int wsum[32];
    if (lane == 31) wsum[wid] = inc;
    __syncthreads();
    if (wid == 0) {
        int w = wsum[lane];
        int wi = w;
#pragma unroll
        for (int off = 1; off < 32; off <<= 1) {
            int y = __shfl_up_sync(0xFFFFFFFFu, wi, off);
            if (lane >= off) wi += y;
        }
        wsum[lane] = wi - w;
    }
    __syncthreads();
    int ex = (inc - tsum) + wsum[wid];
    int run = ex;
#pragma unroll
    for (int c = 0; c < CH; c++) {
        int idx = base + c;
        if (idx < NN) sc[idx] = run;
        run += vals[c];
    }
    __syncthreads();

    for (int i = tid; i < NN; i += 1024) g_off[i] = sc[i];
    if (tid == 1023) g_off[NN] = run;
}

// ---------------- scatter edges into CSR: EB edges per thread -----------------
__global__ void fill_kernel(const void* __restrict__ edge) {
    int e0 = (blockIdx.x * blockDim.x + threadIdx.x) * EB;
    if (e0 >= ET) return;
    int is64 = g_is64;
    int s[EB], d[EB];
#pragma unroll
    for (int q = 0; q < EB; q++) {
        int e = e0 + q;
        s[q] = -1; d[q] = -1;
        if (e < ET) {
            if (e < EE) {
                s[q] = edge_at(edge, (long long)e, is64);
                d[q] = edge_at(edge, (long long)EE + e, is64);
            } else {
                s[q] = e - EE; d[q] = e - EE;
            }
        }
    }
#pragma unroll
    for (int q = 0; q < EB; q++) {
        if ((unsigned)d[q] >= NN || (unsigned)s[q] >= NN) continue;
        int pos = g_off[d[q]] + atomicAdd(&g_cursor[d[q]], 1);
        if ((unsigned)pos < ET) g_src[pos] = s[q];
    }
}

// ---------------- softmax + weighted aggregation ------------------------------
// 128 threads per node.
// Softmax phase: warp w handles head w (unchanged).
// Gather phase: thread (half = tid>>6, sub = tid&63) owns 8 channels
// [sub*8, sub*8+8) via one uint4 fp16 load; warps {0,1} take even edges,
// warps {2,3} take odd edges. Partial accumulators combined via smem.
__global__ void __launch_bounds__(128) agg_kernel(
        const float* __restrict__ bias, float* __restrict__ out) {
    const int i     = blockIdx.x;
    const int tid   = threadIdx.x;
    const int wid   = tid >> 5;          // softmax head
    const int lane  = tid & 31;
    const int half  = tid >> 6;          // edge parity for gather
    const int sub   = tid & 63;          // channel group
    const int chead = sub >> 4;          // head owning this thread's channels
    const int beg   = g_off[i];
    const int deg   = g_off[i + 1] - beg;

    __shared__ float s_e[HH * CAP];      // logits -> exp weights per head
    __shared__ int   s_soff[CAP];        // precomputed uint4 row offsets (s*64)
    __shared__ float s_scale[HH];
    __shared__ float s_inv[HH];

    const float4 adst = *(const float4*)&g_adst[i * HH];
    const uint4* hrow = (const uint4*)g_h2;      // 64 uint4 per node row

    float m_run = -INFINITY;
    float s_run = 0.f;
    float acc[8];
#pragma unroll
    for (int c = 0; c < 8; c++) acc[c] = 0.f;

    for (int c0 = 0; c0 < deg; c0 += CAP) {
        const int cl = min(CAP, deg - c0);

        // load chunk: row offsets + 4 head logits per edge
        for (int j = tid; j < cl; j += 128) {
            int s = g_src[beg + c0 + j];
            s_soff[j] = s * (HC / 8);    // uint4 index of row start
            float4 a = *(const float4*)&g_asrc[s * HH];
            float l0 = a.x + adst.x; l0 = (l0 > 0.f) ? l0 : 0.2f * l0;
            float l1 = a.y + adst.y; l1 = (l1 > 0.f) ? l1 : 0.2f * l1;
            float l2 = a.z + adst.z; l2 = (l2 > 0.f) ? l2 : 0.2f * l2;
            float l3 = a.w + adst.w; l3 = (l3 > 0.f) ? l3 : 0.2f * l3;
            s_e[0 * CAP + j] = l0;
            s_e[1 * CAP + j] = l1;
            s_e[2 * CAP + j] = l2;
            s_e[3 * CAP + j] = l3;
        }
        __syncthreads();

        // per-head chunk max (warp wid handles head wid)
        float m_new = -INFINITY;
        for (int j = lane; j < cl; j += 32)
            m_new = fmaxf(m_new, s_e[wid * CAP + j]);
#pragma unroll
        for (int off = 16; off > 0; off >>= 1)
            m_new = fmaxf(m_new, __shfl_xor_sync(0xFFFFFFFFu, m_new, off));

        float m2 = fmaxf(m_run, m_new);
        float scale = __expf(m_run - m2);   // exp(-inf)=0 on first chunk

        float csum = 0.f;
        for (int j = lane; j < cl; j += 32) {
            float e = __expf(s_e[wid * CAP + j] - m2);
            s_e[wid * CAP + j] = e;
            csum += e;
        }
#pragma unroll
        for (int off = 16; off > 0; off >>= 1)
            csum += __shfl_xor_sync(0xFFFFFFFFu, csum, off);

        s_run = s_run * scale + csum;
        m_run = m2;
        if (lane == 0) s_scale[wid] = scale;
        __syncthreads();

        // rescale accumulators by the channel-head's factor
        float mysc = s_scale[chead];
#pragma unroll
        for (int c = 0; c < 8; c++) acc[c] *= mysc;

        // gather: 2 warps per edge, one uint4 (8 fp16 channels) per thread
        const float* s_eh = &s_e[chead * CAP];
#pragma unroll 4
        for (int k = half; k < cl; k += 2) {
            float al = s_eh[k];
            uint4 u = hrow[s_soff[k] + sub];
            float2 f0 = __half22float2(*(__half2*)&u.x);
            float2 f1 = __half22float2(*(__half2*)&u.y);
            float2 f2 = __half22float2(*(__half2*)&u.z);
            float2 f3 = __half22float2(*(__half2*)&u.w);
            acc[0] += al * f0.x; acc[1] += al * f0.y;
            acc[2] += al * f1.x; acc[3] += al * f1.y;
            acc[4] += al * f2.x; acc[5] += al * f2.y;
            acc[6] += al * f3.x; acc[7] += al * f3.y;
        }
        __syncthreads();
    }

    if (lane == 0) s_inv[wid] = 1.f / (s_run + 1e-16f);
    __syncthreads();

    // combine the two edge-parity partials (reuse s_e as scratch)
    if (half == 1) {
#pragma unroll
        for (int c = 0; c < 8; c++) s_e[sub * 8 + c] = acc[c];
    }
    __syncthreads();
    if (half == 0) {
        float inv = s_inv[chead];
        float4 b0 = *(const float4*)&bias[sub * 8];
        float4 b1 = *(const float4*)&bias[sub * 8 + 4];
        float4 o0, o1;
        o0.x = (acc[0] + s_e[sub * 8 + 0]) * inv + b0.x;
        o0.y = (acc[1] + s_e[sub * 8 + 1]) * inv + b0.y;
        o0.z = (acc[2] + s_e[sub * 8 + 2]) * inv + b0.z;
        o0.w = (acc[3] + s_e[sub * 8 + 3]) * inv + b0.w;
        o1.x = (acc[4] + s_e[sub * 8 + 4]) * inv + b1.x;
        o1.y = (acc[5] + s_e[sub * 8 + 5]) * inv + b1.y;
        o1.z = (acc[6] + s_e[sub * 8 + 6]) * inv + b1.z;
        o1.w = (acc[7] + s_e[sub * 8 + 7]) * inv + b1.w;
        *(float4*)&out[(size_t)i * HC + sub * 8]     = o0;
        *(float4*)&out[(size_t)i * HC + sub * 8 + 4] = o1;
    }
}

// ---------------- launch -------------------------------------------------------
// Two streams: GEMM (x,W only) runs concurrently with the CSR build
// (edge only); both join before agg. Streams/events created once, before
// graph capture.
extern "C" void kernel_launch(void* const* d_in, const int* in_sizes, int n_in,
                              void* d_out, int out_size) {
    const float* x       = (const float*)d_in[0];
    const float* W       = (const float*)d_in[1];
    const float* att_src = (const float*)d_in[2];
    const float* att_dst = (const float*)d_in[3];
    const float* bias    = (const float*)d_in[4];
    const void*  edge    = d_in[5];
    float*       out     = (float*)d_out;

    static cudaStream_t s1 = nullptr;
    static cudaEvent_t  ev_fork = nullptr, ev_gemm = nullptr;
    if (s1 == nullptr) {
        cudaStreamCreateWithFlags(&s1, cudaStreamNonBlocking);
        cudaEventCreateWithFlags(&ev_fork, cudaEventDisableTiming);
        cudaEventCreateWithFlags(&ev_gemm, cudaEventDisableTiming);
    }

    cudaEventRecord(ev_fork, 0);
    cudaStreamWaitEvent(s1, ev_fork, 0);
    gemm_kernel<<<dim3((NN + 127) / 128, HH), 256, 0, s1>>>(x, W, att_src, att_dst);
    cudaEventRecord(ev_gemm, s1);

    setup_kernel<<<(NN + 255) / 256, 256>>>((const int*)edge);
    count_kernel<<<(ET + 256 * EB - 1) / (256 * EB), 256>>>(edge);
    scan_kernel<<<1, 1024>>>();
    fill_kernel<<<(ET + 256 * EB - 1) / (256 * EB), 256>>>(edge);

    cudaStreamWaitEvent(0, ev_gemm, 0);
    agg_kernel<<<NN, 128>>>(bias, out);
}